// round 9
// baseline (speedup 1.0000x reference)
#include <cuda_runtime.h>
#include <cuda_fp16.h>
#include <cstdint>

// SO3Linear via mma.sync fp16 (HMMA), single-MMA scheme (calibrated rel_err ~3e-4).
// R7: smem-staged coalesced epilogue. Direct STG.64 scatter cost 8 L1 lines per
// instr (1024 wf/tile); now accums go through a padded smem stage and leave as
// full-row STG.128 (256+256+256 wf). 56KB smem keeps 4 CTAs/SM.

#define BATCH    16384
#define NUM_M    25
#define IN_F     128
#define OUT_F    128
#define TILE_B   64
#define NTILE    4
#define NTHREADS 256

// W image per l: 32KB = 2 k-chunks (k 0..63 | 64..127) of 128 rows x 128B.
#define W_L_BYTES   32768
#define W_CH_STRIDE 16384
// smem: W at 0 (32KB), A at 32KB (2 chunks x 8KB), stage overlaps A (needs 17408B).
#define A_OFF       32768
#define A_CH_STRIDE 8192
#define STAGE_OFF   32768
#define STAGE_W     136        // words per stage row (conflict-free pad)
#define SMEM_BYTES  57344      // 56KB -> floor(228/56) = 4 CTAs/SM

#define SWZ(b) ((b) ^ (((b) >> 3) & 0x70))

__device__ __align__(128) uint8_t g_wprep[5 * W_L_BYTES];

__device__ __forceinline__ uint32_t smem_u32(const void* p) {
    uint32_t a;
    asm("{ .reg .u64 t; cvta.to.shared.u64 t, %1; cvt.u32.u64 %0, t; }" : "=r"(a) : "l"(p));
    return a;
}

#define LDSM4(r, addr) \
    asm volatile("ldmatrix.sync.aligned.m8n8.x4.shared.b16 {%0,%1,%2,%3}, [%4];" \
        : "=r"((r)[0]), "=r"((r)[1]), "=r"((r)[2]), "=r"((r)[3]) : "r"(addr))

#define MMA_F16(c, a, b0_, b1_) \
    asm volatile("mma.sync.aligned.m16n8k16.row.col.f32.f16.f16.f32 " \
        "{%0,%1,%2,%3},{%4,%5,%6,%7},{%8,%9},{%0,%1,%2,%3};" \
        : "+f"((c)[0]), "+f"((c)[1]), "+f"((c)[2]), "+f"((c)[3]) \
        : "r"((a)[0]), "r"((a)[1]), "r"((a)[2]), "r"((a)[3]), "r"(b0_), "r"(b1_))

__device__ __forceinline__ uint32_t pack_h2(float x, float y) {
    __half2 p = __floats2half2_rn(x, y);
    return *reinterpret_cast<uint32_t*>(&p);
}

// ---- Prep: W[l] -> centered fp16, SW128 smem-image layout in global ----
__global__ void so3_prep_w(const float* __restrict__ w) {
    const int l   = blockIdx.x;
    const int tid = threadIdx.x;
    const float bound = 0.088388347648318447f;  // 1/sqrt(128)
    uint8_t* dst = g_wprep + (size_t)l * W_L_BYTES;
    const float* src = w + (size_t)l * OUT_F * IN_F;
#pragma unroll
    for (int it = 0; it < 16; ++it) {
        int li = it * NTHREADS + tid;
        int r  = li >> 5;
        int q  = li & 31;
        uint32_t soff = (uint32_t)(q >> 4) * W_CH_STRIDE +
                        SWZ((uint32_t)(r * 128 + (q & 15) * 8));
        float4 v = *reinterpret_cast<const float4*>(src + (size_t)r * IN_F + q * 4);
        v.x -= bound; v.y -= bound; v.z -= bound; v.w -= bound;
        *reinterpret_cast<uint2*>(dst + soff) =
            make_uint2(pack_h2(v.x, v.y), pack_h2(v.z, v.w));
    }
}

// ---- Main kernel ----
__global__ __launch_bounds__(NTHREADS, 4)
void so3linear_hmma_kernel(const float* __restrict__ in,
                           const float* __restrict__ bias,
                           float* __restrict__ out) {
    extern __shared__ char smem[];
    const uint32_t sb = smem_u32(smem);
    float* stage = reinterpret_cast<float*>(smem + STAGE_OFF);

    const int tid  = threadIdx.x;
    const int wid  = tid >> 5;
    const int lane = tid & 31;
    const int m    = blockIdx.y;
    const int l    = (m >= 16) ? 4 : (m >= 9) ? 3 : (m >= 4) ? 2 : (m >= 1) ? 1 : 0;

    // ---- W: flat 32KB cp.async from prepped image ----
    {
        const uint8_t* wsrc = g_wprep + (size_t)l * W_L_BYTES;
#pragma unroll
        for (int it = 0; it < 8; ++it) {
            uint32_t off = (uint32_t)(it * NTHREADS + tid) * 16u;
            asm volatile("cp.async.cg.shared.global [%0], [%1], 16;"
                         :: "r"(sb + off), "l"(wsrc + off) : "memory");
        }
        asm volatile("cp.async.commit_group;" ::: "memory");
    }

    // Per-thread constants for A conversion
    const int cr = tid >> 5;
    const int cq = tid & 31;
    const uint32_t a_soff = (uint32_t)(cq >> 4) * A_CH_STRIDE +
                            SWZ((uint32_t)(cr * 128 + (cq & 15) * 8));

    // Warp tile: wid&1 -> m block (32 rows), wid>>1 -> n block (32 cols)
    const int m0 = (wid & 1) * 32;
    const int n0 = (wid >> 1) * 32;
    const int row_in = (lane & 7) + ((lane >> 3) & 1) * 8;
    const int kadd   = (lane >> 4) * 8;

    // Bias for the stage-read lane mapping (col = lane*4)
    float4 bv4 = make_float4(0.f, 0.f, 0.f, 0.f);
    if (m == 0) bv4 = *reinterpret_cast<const float4*>(bias + lane * 4);

    for (int t = 0; t < NTILE; ++t) {
        const int b0 = (blockIdx.x * NTILE + t) * TILE_B;
        const float* aBase = in + ((size_t)b0 * NUM_M + m) * IN_F;

        // ---- Convert A tile (64x128 fp32 -> fp16 RN, swizzled) ----
#pragma unroll
        for (int it = 0; it < 8; ++it) {
            int r = cr + it * 8;
            uint32_t soff = a_soff + (uint32_t)it * (8 * 128);
            float4 v = *reinterpret_cast<const float4*>(
                aBase + (size_t)r * (NUM_M * IN_F) + cq * 4);
            *reinterpret_cast<uint2*>(smem + A_OFF + soff) =
                make_uint2(pack_h2(v.x, v.y), pack_h2(v.z, v.w));
        }
        asm volatile("cp.async.wait_group 0;" ::: "memory");
        __syncthreads();

        // ---- MMA: 8 k-steps ----
        float acc[2][4][4];
#pragma unroll
        for (int a = 0; a < 2; ++a)
#pragma unroll
            for (int b = 0; b < 4; ++b)
#pragma unroll
                for (int c = 0; c < 4; ++c) acc[a][b][c] = 0.0f;

#pragma unroll
        for (int ks = 0; ks < 8; ++ks) {
            const int kc    = ks * 16 + kadd;
            const int chunk = kc >> 6;
            const int kwi   = (kc & 63) * 2;

            uint32_t ah[2][4], wh[2][4];
#pragma unroll
            for (int mt = 0; mt < 2; ++mt) {
                uint32_t addr = sb + A_OFF + (uint32_t)chunk * A_CH_STRIDE +
                                SWZ((uint32_t)((m0 + mt * 16 + row_in) * 128 + kwi));
                LDSM4(ah[mt], addr);
            }
#pragma unroll
            for (int g = 0; g < 2; ++g) {
                uint32_t addr = sb + (uint32_t)chunk * W_CH_STRIDE +
                                SWZ((uint32_t)((n0 + g * 16 + row_in) * 128 + kwi));
                LDSM4(wh[g], addr);
            }
#pragma unroll
            for (int mt = 0; mt < 2; ++mt) {
#pragma unroll
                for (int nt = 0; nt < 4; ++nt) {
                    const int g = nt >> 1, o = nt & 1;
                    MMA_F16(acc[mt][nt], ah[mt], wh[g][o], wh[g][2 + o]);
                }
            }
        }

        // ---- Staged epilogue: 2 passes of 32 rows, coalesced STG.128 ----
#pragma unroll
        for (int mt = 0; mt < 2; ++mt) {
            __syncthreads();   // mt=0: MMA done (stage overlaps A); mt=1: prior reads done
            // STS: scatter accums into padded stage rows
#pragma unroll
            for (int nt = 0; nt < 4; ++nt) {
#pragma unroll
                for (int h = 0; h < 2; ++h) {
                    int sr  = (wid & 1) * 16 + (lane >> 2) + h * 8;
                    int col = n0 + nt * 8 + (lane & 3) * 2;
                    *reinterpret_cast<float2*>(stage + sr * STAGE_W + col) =
                        make_float2(acc[mt][nt][2 * h], acc[mt][nt][2 * h + 1]);
                }
            }
            __syncthreads();
            // LDS + coalesced STG: one full 512B row per warp-instr
#pragma unroll
            for (int it = 0; it < 4; ++it) {
                int sr = wid * 4 + it;
                int gr = b0 + ((sr >> 4) * 32) + mt * 16 + (sr & 15);
                float4 v = *reinterpret_cast<const float4*>(stage + sr * STAGE_W + lane * 4);
                v.x += bv4.x; v.y += bv4.y; v.z += bv4.z; v.w += bv4.w;
                __stcs(reinterpret_cast<float4*>(
                           out + ((size_t)gr * NUM_M + m) * OUT_F + lane * 4), v);
            }
        }
        __syncthreads();   // stage (= A region) reused by next tile's convert
    }
}

extern "C" void kernel_launch(void* const* d_in, const int* in_sizes, int n_in,
                              void* d_out, int out_size) {
    const float* in   = (const float*)d_in[0];  // [16384, 25, 128]
    const float* w    = (const float*)d_in[1];  // [5, 128, 128]
    const float* bias = (const float*)d_in[2];  // [128]
    float* out        = (float*)d_out;          // [16384, 25, 128]

    so3_prep_w<<<5, NTHREADS>>>(w);

    cudaFuncSetAttribute(so3linear_hmma_kernel,
                         cudaFuncAttributeMaxDynamicSharedMemorySize, SMEM_BYTES);

    dim3 grid(BATCH / (TILE_B * NTILE), NUM_M);  // (64, 25) = 1600 CTAs
    so3linear_hmma_kernel<<<grid, NTHREADS, SMEM_BYTES>>>(in, bias, out);
}